// round 16
// baseline (speedup 1.0000x reference)
#include <cuda_runtime.h>
#include <cuda_fp16.h>
#include <stdint.h>
#include <math.h>

#define TOK 18432
#define SCALE 0.35355339059327373f
#define W_PS  786432
#define W_QT  1048576
#define W_PT  1835008

static __device__ __half g_Y [TOK*1536];
static __device__ float g_x1[TOK*512];
static __device__ __half g_A[TOK*512];
static __device__ __half g_W[4096*512];

static __device__ __forceinline__ uint32_t s2u(const void* p) {
    uint32_t a;
    asm("{ .reg .u64 t; cvta.to.shared.u64 t, %1; cvt.u32.u64 %0, t; }" : "=r"(a) : "l"(p));
    return a;
}
static __device__ __forceinline__ void ldm4(uint32_t* r, uint32_t addr) {
    asm volatile("ldmatrix.sync.aligned.m8n8.x4.shared.b16 {%0,%1,%2,%3}, [%4];"
        : "=r"(r[0]), "=r"(r[1]), "=r"(r[2]), "=r"(r[3]) : "r"(addr));
}
static __device__ __forceinline__ void ldm4t(uint32_t* r, uint32_t addr) {
    asm volatile("ldmatrix.sync.aligned.m8n8.x4.trans.shared.b16 {%0,%1,%2,%3}, [%4];"
        : "=r"(r[0]), "=r"(r[1]), "=r"(r[2]), "=r"(r[3]) : "r"(addr));
}
static __device__ __forceinline__ void mma16816(float* d, const uint32_t* a, uint32_t b0, uint32_t b1) {
    asm volatile("mma.sync.aligned.m16n8k16.row.col.f32.f16.f16.f32 "
        "{%0,%1,%2,%3}, {%4,%5,%6,%7}, {%8,%9}, {%0,%1,%2,%3};"
        : "+f"(d[0]), "+f"(d[1]), "+f"(d[2]), "+f"(d[3])
        : "r"(a[0]), "r"(a[1]), "r"(a[2]), "r"(a[3]), "r"(b0), "r"(b1));
}
static __device__ __forceinline__ void cpasync16(uint32_t saddr, const void* g) {
    asm volatile("cp.async.cg.shared.global [%0], [%1], 16;" :: "r"(saddr), "l"(g));
}
static __device__ __forceinline__ uint32_t packh(float a, float b) {
    __half2 t = __floats2half2_rn(a, b);
    return *reinterpret_cast<uint32_t*>(&t);
}

// ---------------- fused spatial GN: stats + normalize + transpose, one x read ----------------
__global__ __launch_bounds__(256) void gn_norm_s(const float* __restrict__ x,
        const float* __restrict__ gw, const float* __restrict__ gb) {
    __shared__ float buf[9216];
    __shared__ float rs[8], rss[8], red[2], sgw[16], sgb[16];
    int bt = blockIdx.x, g = blockIdx.y;
    int b = bt >> 4, t = bt & 15;
    const float* base = x + ((size_t)(b*512 + g*16))*9216 + (size_t)t*576;
    float s = 0.f, ss = 0.f;
    for (int e = threadIdx.x; e < 9216; e += 256) {
        int cc = e / 576, hw = e - cc*576;
        float v = base[(size_t)cc*9216 + hw];
        buf[e] = v;
        s += v; ss += v*v;
    }
    if (threadIdx.x < 16) {
        sgw[threadIdx.x] = gw[g*16 + threadIdx.x];
        sgb[threadIdx.x] = gb[g*16 + threadIdx.x];
    }
    #pragma unroll
    for (int o = 16; o; o >>= 1) {
        s  += __shfl_xor_sync(0xffffffffu, s,  o);
        ss += __shfl_xor_sync(0xffffffffu, ss, o);
    }
    int w = threadIdx.x >> 5;
    if ((threadIdx.x & 31) == 0) { rs[w] = s; rss[w] = ss; }
    __syncthreads();
    if (threadIdx.x == 0) {
        s = 0.f; ss = 0.f;
        #pragma unroll
        for (int i = 0; i < 8; i++) { s += rs[i]; ss += rss[i]; }
        float mean = s * (1.f/9216.f);
        float var  = ss * (1.f/9216.f) - mean*mean;
        red[0] = mean; red[1] = rsqrtf(var + 1e-5f);
    }
    __syncthreads();
    float mean = red[0], rstd = red[1];
    for (int hw = threadIdx.x; hw < 576; hw += 256) {
        __half tmp[16];
        #pragma unroll
        for (int cc = 0; cc < 16; cc++)
            tmp[cc] = __float2half_rn((buf[cc*576 + hw] - mean)*rstd*sgw[cc] + sgb[cc]);
        uint4* dst = (uint4*)(g_A + ((size_t)(bt*576 + hw))*512 + g*16);
        dst[0] = *(uint4*)&tmp[0];
        dst[1] = *(uint4*)&tmp[8];
    }
}

// ---------------- fused temporal GN ----------------
__global__ __launch_bounds__(256) void gn_norm_t(const float* __restrict__ gw,
                                                 const float* __restrict__ gb) {
    __shared__ float buf[16*16*33];
    __shared__ float part[8][32], partss[8][32], stat[2][32], sgw[16], sgb[16];
    int b = blockIdx.x, hw0 = blockIdx.y*32, g = blockIdx.z;
    int hwl = threadIdx.x & 31, slice = threadIdx.x >> 5;
    float s = 0.f, ss = 0.f;
    #pragma unroll
    for (int i = 0; i < 32; i++) {
        int p = slice*32 + i;
        int cc = p >> 4, t = p & 15;
        float v = g_x1[(((size_t)(b*512 + g*16 + cc))*16 + t)*576 + hw0 + hwl];
        buf[(cc*16 + t)*33 + hwl] = v;
        s += v; ss += v*v;
    }
    part[slice][hwl] = s;
    partss[slice][hwl] = ss;
    if (threadIdx.x >= 64 && threadIdx.x < 80) {
        sgw[threadIdx.x-64] = gw[g*16 + threadIdx.x-64];
        sgb[threadIdx.x-64] = gb[g*16 + threadIdx.x-64];
    }
    __syncthreads();
    if (threadIdx.x < 32) {
        float ts = 0.f, tss = 0.f;
        #pragma unroll
        for (int k = 0; k < 8; k++) { ts += part[k][threadIdx.x]; tss += partss[k][threadIdx.x]; }
        float mean = ts*(1.f/256.f);
        float var  = tss*(1.f/256.f) - mean*mean;
        stat[0][threadIdx.x] = mean;
        stat[1][threadIdx.x] = rsqrtf(var + 1e-5f);
    }
    __syncthreads();
    for (int pp = threadIdx.x; pp < 512; pp += 256) {
        int h2 = pp >> 4, t = pp & 15;
        float mean = stat[0][h2], rstd = stat[1][h2];
        __half tmp[16];
        #pragma unroll
        for (int cc = 0; cc < 16; cc++)
            tmp[cc] = __float2half_rn((buf[(cc*16 + t)*33 + h2] - mean)*rstd*sgw[cc] + sgb[cc]);
        uint4* dst = (uint4*)(g_A + ((size_t)((b*576 + hw0 + h2)*16 + t))*512 + g*16);
        dst[0] = *(uint4*)&tmp[0];
        dst[1] = *(uint4*)&tmp[8];
    }
}

// ---------------- weight convert ----------------
__global__ void wconv4(const float* __restrict__ wqs, const float* __restrict__ wps,
                       const float* __restrict__ wqt, const float* __restrict__ wpt) {
    int i = blockIdx.x*256 + threadIdx.x;
    float v;
    if (i < W_PS)       v = wqs[i];
    else if (i < W_QT)  v = wps[i - W_PS];
    else if (i < W_PT)  v = wqt[i - W_QT];
    else                v = wpt[i - W_PT];
    g_W[i] = __float2half_rn(v);
}

// ---------------- fp16 HMMA GEMM, cp.async 2-stage, fp16 output (qkv) ----------------
#define SPAD 72
#define GEMM_SMEM (2*36864)
#define PROJ_SMEM 73728
__global__ __launch_bounds__(256) void gemm_mma(
    const __half* __restrict__ A, const __half* __restrict__ B,
    const float* __restrict__ bias, __half* __restrict__ Y, int N) {
    extern __shared__ __half sm[];
    uint32_t smb = s2u(sm);
    int tid = threadIdx.x, wid = tid >> 5, lane = tid & 31;
    int wm = wid >> 2, wn = wid & 3;
    int m0 = blockIdx.y*128, n0 = blockIdx.x*128;
    const __half* pA = A + (size_t)m0*512;
    const __half* pB = B + (size_t)n0*512;

    float acc[4][4][4];
    #pragma unroll
    for (int i = 0; i < 4; i++)
        #pragma unroll
        for (int j = 0; j < 4; j++)
            #pragma unroll
            for (int k = 0; k < 4; k++) acc[i][j][k] = 0.f;

    int lrow = lane & 15, lcol = (lane >> 4) << 3;
    uint32_t aoff = (uint32_t)(( (wm*64 + lrow) * SPAD + lcol ) * 2);
    uint32_t boff = (uint32_t)(( (wn*32 + lrow) * SPAD + lcol ) * 2 + 18432);

    #pragma unroll
    for (int i = 0; i < 4; i++) {
        int idx = tid + i*256;
        int r = idx >> 3, c8 = (idx & 7) << 3;
        size_t go = (size_t)r*512 + c8;
        uint32_t so = smb + (uint32_t)((r*SPAD + c8)*2);
        cpasync16(so,         pA + go);
        cpasync16(so + 18432, pB + go);
    }
    asm volatile("cp.async.commit_group;" ::: "memory");

    for (int chunk = 0; chunk < 8; chunk++) {
        if (chunk < 7) {
            int koff = (chunk+1)*64;
            uint32_t stb = smb + ((chunk+1)&1)*36864;
            #pragma unroll
            for (int i = 0; i < 4; i++) {
                int idx = tid + i*256;
                int r = idx >> 3, c8 = (idx & 7) << 3;
                size_t go = (size_t)r*512 + koff + c8;
                uint32_t so = stb + (uint32_t)((r*SPAD + c8)*2);
                cpasync16(so,         pA + go);
                cpasync16(so + 18432, pB + go);
            }
            asm volatile("cp.async.commit_group;" ::: "memory");
            asm volatile("cp.async.wait_group 1;" ::: "memory");
        } else {
            asm volatile("cp.async.wait_group 0;" ::: "memory");
        }
        __syncthreads();
        uint32_t stb = smb + (chunk&1)*36864;
        uint32_t uA = stb + aoff, uB = stb + boff;
        #pragma unroll
        for (int k16 = 0; k16 < 4; k16++) {
            uint32_t kb = k16*32;
            uint32_t af[4][4], bf[2][4];
            #pragma unroll
            for (int mi = 0; mi < 4; mi++) ldm4(af[mi], uA + mi*16*SPAD*2 + kb);
            #pragma unroll
            for (int nj = 0; nj < 2; nj++) ldm4(bf[nj], uB + nj*16*SPAD*2 + kb);
            #pragma unroll
            for (int mi = 0; mi < 4; mi++)
                #pragma unroll
                for (int ni = 0; ni < 4; ni++) {
                    int nj = ni >> 1, hf = ni & 1;
                    mma16816(acc[mi][ni], af[mi], bf[nj][hf], bf[nj][hf+2]);
                }
        }
        __syncthreads();
    }
    int rbase = m0 + wm*64 + (lane >> 2);
    int cbase = n0 + wn*32 + (lane & 3)*2;
    #pragma unroll
    for (int mi = 0; mi < 4; mi++)
        #pragma unroll
        for (int ni = 0; ni < 4; ni++) {
            int col = cbase + ni*8;
            float2 bv = *(const float2*)(bias + col);
            int r0 = rbase + mi*16;
            *(uint32_t*)(Y + (size_t)r0*N + col)     = packh(acc[mi][ni][0] + bv.x, acc[mi][ni][1] + bv.y);
            *(uint32_t*)(Y + (size_t)(r0+8)*N + col) = packh(acc[mi][ni][2] + bv.x, acc[mi][ni][3] + bv.y);
        }
}

// ---- pipelined fp16 GEMM mainloop + fp32 ps staging (proj variants) ----
#define GEMM_BODY_P()                                                            \
    uint32_t smb = s2u(sm);                                                      \
    float acc[4][4][4];                                                          \
    _Pragma("unroll")                                                            \
    for (int i = 0; i < 4; i++)                                                  \
        _Pragma("unroll")                                                        \
        for (int j = 0; j < 4; j++)                                              \
            _Pragma("unroll")                                                    \
            for (int k = 0; k < 4; k++) acc[i][j][k] = 0.f;                      \
    int lrow = lane & 15, lcol = (lane >> 4) << 3;                               \
    uint32_t aoff = (uint32_t)(( (wm*64 + lrow) * SPAD + lcol ) * 2);            \
    uint32_t boff = (uint32_t)(( (wn*32 + lrow) * SPAD + lcol ) * 2 + 18432);    \
    _Pragma("unroll")                                                            \
    for (int i = 0; i < 4; i++) {                                                \
        int idx = tid + i*256;                                                   \
        int r = idx >> 3, c8 = (idx & 7) << 3;                                   \
        size_t go = (size_t)r*512 + c8;                                          \
        uint32_t so = smb + (uint32_t)((r*SPAD + c8)*2);                         \
        cpasync16(so,         pA + go);                                          \
        cpasync16(so + 18432, pB + go);                                          \
    }                                                                            \
    asm volatile("cp.async.commit_group;" ::: "memory");                         \
    for (int chunk = 0; chunk < 8; chunk++) {                                    \
        if (chunk < 7) {                                                         \
            int koff = (chunk+1)*64;                                             \
            uint32_t stb = smb + ((chunk+1)&1)*36864;                            \
            _Pragma("unroll")                                                    \
            for (int i = 0; i < 4; i++) {                                        \
                int idx = tid + i*256;                                           \
                int r = idx >> 3, c8 = (idx & 7) << 3;                           \
                size_t go = (size_t)r*512 + koff + c8;                           \
                uint32_t so = stb + (uint32_t)((r*SPAD + c8)*2);                 \
                cpasync16(so,         pA + go);                                  \
                cpasync16(so + 18432, pB + go);                                  \
            }                                                                    \
            asm volatile("cp.async.commit_group;" ::: "memory");                 \
            asm volatile("cp.async.wait_group 1;" ::: "memory");                 \
        } else {                                                                 \
            asm volatile("cp.async.wait_group 0;" ::: "memory");                 \
        }                                                                        \
        __syncthreads();                                                         \
        uint32_t stb = smb + (chunk&1)*36864;                                    \
        uint32_t uA = stb + aoff, uB = stb + boff;                               \
        _Pragma("unroll")                                                        \
        for (int k16 = 0; k16 < 4; k16++) {                                      \
            uint32_t kb = k16*32;                                                \
            uint32_t af[4][4], bf[2][4];                                         \
            _Pragma("unroll")                                                    \
            for (int mi = 0; mi < 4; mi++) ldm4(af[mi], uA + mi*16*SPAD*2 + kb); \
            _Pragma("unroll")                                                    \
            for (int nj = 0; nj < 2; nj++) ldm4(bf[nj], uB + nj*16*SPAD*2 + kb); \
            _Pragma("unroll")                                                    \
            for (int mi = 0; mi < 4; mi++)                                       \
                _Pragma("unroll")                                                \
                for (int ni = 0; ni < 4; ni++) {                                 \
                    int nj = ni >> 1, hf = ni & 1;                               \
                    mma16816(acc[mi][ni], af[mi], bf[nj][hf], bf[nj][hf+2]);     \
                }                                                                \
        }                                                                        \
        __syncthreads();                                                         \
    }                                                                            \
    float* ps = (float*)sm;                                                      \
    {                                                                            \
        int rb = wm*64 + (lane >> 2);                                            \
        int cb = wn*32 + (lane & 3)*2;                                           \
        _Pragma("unroll")                                                        \
        for (int mi = 0; mi < 4; mi++)                                           \
            _Pragma("unroll")                                                    \
            for (int ni = 0; ni < 4; ni++) {                                     \
                int c = cb + ni*8;                                               \
                float2 bv = *(const float2*)(bias + n0 + c);                     \
                int r0 = rb + mi*16;                                             \
                ps[c*132 + r0]         = acc[mi][ni][0] + bv.x;                  \
                ps[(c+1)*132 + r0]     = acc[mi][ni][1] + bv.y;                  \
                ps[c*132 + r0 + 8]     = acc[mi][ni][2] + bv.x;                  \
                ps[(c+1)*132 + r0 + 8] = acc[mi][ni][3] + bv.y;                  \
            }                                                                    \
    }                                                                            \
    __syncthreads();

// ---- proj_s GEMM + fused spatial residual: x1 = x + C^T ----
__global__ __launch_bounds__(256) void gemm_proj_resid(
    const __half* __restrict__ A, const __half* __restrict__ B,
    const float* __restrict__ bias, const float* __restrict__ x, float* __restrict__ x1) {
    extern __shared__ __half sm[];
    int tid = threadIdx.x, wid = tid >> 5, lane = tid & 31;
    int wm = wid >> 2, wn = wid & 3;
    int m0 = blockIdx.y*128, n0 = blockIdx.x*128;
    const __half* pA = A + (size_t)m0*512;
    const __half* pB = B + (size_t)n0*512;
    GEMM_BODY_P()
    {
        int w = tid >> 5;
        int r = (tid & 31)*4;
        int tk = m0 + r;
        int ns = tk / 576, hw = tk - ns*576;
        int b = ns >> 4, t = ns & 15;
        #pragma unroll
        for (int i = 0; i < 16; i++) {
            int c = w + i*8;
            float4 v = *(float4*)&ps[c*132 + r];
            size_t o = (((size_t)b*512 + n0 + c)*16 + t)*576 + hw;
            float4 xi = *(const float4*)(x + o);
            v.x += xi.x; v.y += xi.y; v.z += xi.z; v.w += xi.w;
            *(float4*)(x1 + o) = v;
        }
    }
}

// ---- proj_t GEMM + fused temporal residual: out = x1 + C^T ----
__global__ __launch_bounds__(256) void gemm_proj_resid_t(
    const __half* __restrict__ A, const __half* __restrict__ B,
    const float* __restrict__ bias, const float* __restrict__ xr, float* __restrict__ outp) {
    extern __shared__ __half sm[];
    int tid = threadIdx.x, wid = tid >> 5, lane = tid & 31;
    int wm = wid >> 2, wn = wid & 3;
    int m0 = blockIdx.y*128, n0 = blockIdx.x*128;
    const __half* pA = A + (size_t)m0*512;
    const __half* pB = B + (size_t)n0*512;
    GEMM_BODY_P()
    {
        int ns2 = m0 >> 4;
        int b = ns2 / 576, hw0 = ns2 - b*576;
        int t = tid & 15;
        #pragma unroll
        for (int it = 0; it < 8; it++) {
            int c = it*16 + (tid >> 4);
            float v[8];
            #pragma unroll
            for (int hwl = 0; hwl < 8; hwl++)
                v[hwl] = ps[c*132 + hwl*16 + t];
            size_t o = (((size_t)b*512 + n0 + c)*16 + t)*576 + hw0;
            float4 x0 = *(const float4*)(xr + o);
            float4 x1v = *(const float4*)(xr + o + 4);
            float4 o0 = { v[0]+x0.x, v[1]+x0.y, v[2]+x0.z, v[3]+x0.w };
            float4 o1 = { v[4]+x1v.x, v[5]+x1v.y, v[6]+x1v.z, v[7]+x1v.w };
            *(float4*)(outp + o)     = o0;
            *(float4*)(outp + o + 4) = o1;
        }
    }
}

// ---------------- spatial attention: K/V-stationary, fixed-shift softmax ----------------
// block = (q-half, h, ns), 288 threads (9 warps x 16 q-rows), 2 passes of 144 rows.
#define AT_SMEM ((144*72 + 2*576*72)*2)
__global__ __launch_bounds__(288) void attn_spatial_mma(const __half* __restrict__ Y,
        __half* __restrict__ O) {
    extern __shared__ __half sb[];
    __half* Qs = sb;                     // 144*72
    __half* Ks = sb + 144*72;            // 576*72
    __half* Vs = sb + 144*72 + 576*72;   // 576*72
    int qh = blockIdx.x, h = blockIdx.y, ns = blockIdx.z;
    int tid = threadIdx.x, wid = tid >> 5, lane = tid & 31;

    // issue full K/V load (cp.async), overlapped with pass-0 Q load below
    {
        uint32_t uKs = s2u(Ks), uVs = s2u(Vs);
        for (int r = tid; r < 576; r += 288) {
            const __half* src = Y + ((size_t)(ns*576 + r))*1536 + 512 + h*64;
            uint32_t ko = uKs + r*144;   // 72 halfs * 2B
            uint32_t vo = uVs + r*144;
            #pragma unroll
            for (int j = 0; j < 8; j++) {
                cpasync16(ko + j*16, src + j*8);
                cpasync16(vo + j*16, src + 512 + j*8);
            }
        }
        asm volatile("cp.async.commit_group;" ::: "memory");
    }

    int lrow = lane & 15, lcol = (lane >> 4) << 3;
    uint32_t uQb = s2u(Qs) + ((wid*16 + lrow)*72 + lcol)*2;
    uint32_t uKbb = s2u(Ks) + (lrow*72 + lcol)*2;
    uint32_t uVbb = s2u(Vs) + (lrow*72 + lcol)*2;
    __half2 sc = __float2half2_rn(0.125f);

    #pragma unroll
    for (int pass = 0; pass < 2; pass++) {
        int q0 = (qh*2 + pass)*144;
        if (pass) __syncthreads();      // protect Qs reuse
        {   // load Q rows q0..q0+143 (LDG; overlaps the K/V DMA on pass 0)
            int row = tid >> 1, dh = (tid & 1)*32;
            const __half* src = Y + ((size_t)(ns*576 + q0 + row))*1536 + h*64 + dh;
            #pragma unroll
            for (int j = 0; j < 8; j++) {
                uint2 u = *(const uint2*)(src + j*4);
                __half2 a0 = __hmul2(*(__half2*)&u.x, sc);
                __half2 a1 = __hmul2(*(__half2*)&u.y, sc);
                uint2 o = { *(uint32_t*)&a0, *(uint32_t*)&a1 };
                *(uint2*)(Qs + row*72 + dh + j*4) = o;
            }
        }
        if (pass == 0) asm volatile("cp.async.wait_group 0;" ::: "memory");
        __syncthreads();

        float oacc[8][4];
        float l[2] = {0.f, 0.f};
        #pragma unroll
        for (int t = 0; t < 8; t++)
            #pragma unroll
            for (int e = 0; e < 4; e++) oacc[t][e] = 0.f;

        for (int ch = 0; ch < 9; ch++) {
            uint32_t uK = uKbb + ch*64*144;
            uint32_t uV = uVbb + ch*64*144;
            float sacc[8][4];
            #pragma unroll
            for (int t = 0; t < 8; t++)
                #pragma unroll
                for (int e = 0; e < 4; e++) sacc[t][e] = 0.f;
            #pragma unroll
            for (int k16 = 0; k16 < 4; k16++) {
                uint32_t kb = k16*32;
                uint32_t a4[4];
                ldm4(a4, uQb + kb);
                #pragma unroll
                for (int g = 0; g < 4; g++) {
                    uint32_t k4[4];
                    ldm4(k4, uK + g*16*144 + kb);
                    mma16816(sacc[2*g],   a4, k4[0], k4[2]);
                    mma16816(sacc[2*g+1], a4, k4[1], k4[3]);
                }
            }
            uint32_t phx[8][2];
            #pragma unroll
            for (int hf = 0; hf < 2; hf++) {
                float rs = 0.f;
                #pragma unroll
                for (int t = 0; t < 8; t++) {
                    float p0 = __expf(sacc[t][2*hf]);
                    float p1 = __expf(sacc[t][2*hf+1]);
                    rs += p0 + p1;
                    phx[t][hf] = packh(p0, p1);
                }
                rs += __shfl_xor_sync(0xffffffffu, rs, 1);
                rs += __shfl_xor_sync(0xffffffffu, rs, 2);
                l[hf] += rs;
            }
            #pragma unroll
            for (int g = 0; g < 4; g++) {
                uint32_t pa[4] = {phx[2*g][0], phx[2*g][1], phx[2*g+1][0], phx[2*g+1][1]};
                #pragma unroll
                for (int dt = 0; dt < 4; dt++) {
                    uint32_t v4[4];
                    ldm4t(v4, uV + g*16*144 + dt*32);
                    mma16816(oacc[2*dt],   pa, v4[0], v4[1]);
                    mma16816(oacc[2*dt+1], pa, v4[2], v4[3]);
                }
            }
        }
        float inv0 = 1.f / l[0], inv1 = 1.f / l[1];
        int r0 = q0 + wid*16 + (lane >> 2);
        int col0 = h*64 + (lane & 3)*2;
        #pragma unroll
        for (int t = 0; t < 8; t++) {
            int col = col0 + t*8;
            size_t offA = ((size_t)(ns*576 + r0))*512 + col;
            size_t offB = ((size_t)(ns*576 + r0 + 8))*512 + col;
            *(uint32_t*)(O + offA) = packh(oacc[t][0]*inv0, oacc[t][1]*inv0);
            *(uint32_t*)(O + offB) = packh(oacc[t][2]*inv1, oacc[t][3]*inv1);
        }
    }
}

// ---------------- temporal attention (batched 8 samples per block) ----------------
#define TPS 8
__global__ __launch_bounds__(256) void attn_temporal(const __half* __restrict__ Y,
    const float* __restrict__ rpk, const float* __restrict__ rpv,
    __half* __restrict__ O) {
    __shared__ float qs[16][68], ks[16][68], vs[16][68];
    __shared__ float pk[33][68], pvt[33][68], wsm[16][20];
    int h = blockIdx.x, sg = blockIdx.y, tid = threadIdx.x;
    for (int i = tid; i < 33*64; i += 256) {
        pk [i>>6][i&63] = rpk[i];
        pvt[i>>6][i&63] = rpv[i];
    }
    for (int si = 0; si < TPS; si++) {
        int samp = sg*TPS + si;
        __syncthreads();
        {
            int t = tid >> 4, d0 = (tid & 15)*4;
            const __half* base = Y + ((size_t)(samp*16 + t))*1536 + h*64 + d0;
            #pragma unroll
            for (int part = 0; part < 3; part++) {
                uint2 u = *(const uint2*)(base + part*512);
                __half2 p0 = *(__half2*)&u.x, p1 = *(__half2*)&u.y;
                float* dst = (part == 0) ? &qs[t][d0] : (part == 1) ? &ks[t][d0] : &vs[t][d0];
                dst[0] = __half2float(p0.x); dst[1] = __half2float(p0.y);
                dst[2] = __half2float(p1.x); dst[3] = __half2float(p1.y);
            }
        }
        __syncthreads();
        {
            int t = tid >> 4, s = tid & 15;
            float wv = -1e30f;
            if (s <= t) {
                float a = 0.f, bb = 0.f;
                int ri = t - s + 16;
                for (int d = 0; d < 64; d++) {
                    a  += qs[t][d]*ks[s][d];
                    bb += qs[s][d]*pk[ri][d];
                }
                wv = 0.125f*a + SCALE*bb;
            }
            float mx = wv;
            #pragma unroll
            for (int o = 8; o; o >>= 1) mx = fmaxf(mx, __shfl_xor_sync(0xffffffffu, mx, o, 16));
            float e = (s <= t) ? __expf(wv - mx) : 0.f;
            float sum = e;
            #pragma unroll
            for (int o = 8; o; o >>= 1) sum += __shfl_xor_sync(0xffffffffu, sum, o, 16);
            wsm[t][s] = e / sum;
        }
        __syncthreads();
        {
            int t = tid >> 4, d0 = (tid & 15)*4;
            float o0 = 0.f, o1 = 0.f, o2 = 0.f, o3 = 0.f;
            #pragma unroll
            for (int s = 0; s < 16; s++) {
                float p = wsm[t][s];
                int ri = s - t + 16;
                o0 += p*(vs[s][d0+0] + pvt[ri][d0+0]);
                o1 += p*(vs[s][d0+1] + pvt[ri][d0+1]);
                o2 += p*(vs[s][d0+2] + pvt[ri][d0+2]);
                o3 += p*(vs[s][d0+3] + pvt[ri][d0+3]);
            }
            size_t off = ((size_t)(samp*16 + t))*512 + h*64 + d0;
            *(uint32_t*)(O + off)     = packh(o0, o1);
            *(uint32_t*)(O + off + 2) = packh(o2, o3);
        }
    }
}

extern "C" void kernel_launch(void* const* d_in, const int* in_sizes, int n_in,
                              void* d_out, int out_size) {
    const float* x        = (const float*)d_in[0];
    const float* norm_s_w = (const float*)d_in[1];
    const float* norm_s_b = (const float*)d_in[2];
    const float* qkv_s_w  = (const float*)d_in[3];
    const float* qkv_s_b  = (const float*)d_in[4];
    const float* proj_s_w = (const float*)d_in[5];
    const float* proj_s_b = (const float*)d_in[6];
    const float* norm_t_w = (const float*)d_in[7];
    const float* norm_t_b = (const float*)d_in[8];
    const float* qkv_t_w  = (const float*)d_in[9];
    const float* qkv_t_b  = (const float*)d_in[10];
    const float* proj_t_w = (const float*)d_in[11];
    const float* proj_t_b = (const float*)d_in[12];
    const float* rpk      = (const float*)d_in[13];
    const float* rpv      = (const float*)d_in[14];
    float* out = (float*)d_out;

    float *gX1;
    __half *gY, *gA, *gW;
    cudaGetSymbolAddress((void**)&gY,  g_Y);
    cudaGetSymbolAddress((void**)&gX1, g_x1);
    cudaGetSymbolAddress((void**)&gA,  g_A);
    cudaGetSymbolAddress((void**)&gW,  g_W);

    cudaFuncSetAttribute(gemm_mma, cudaFuncAttributeMaxDynamicSharedMemorySize, GEMM_SMEM);
    cudaFuncSetAttribute(gemm_proj_resid, cudaFuncAttributeMaxDynamicSharedMemorySize, PROJ_SMEM);
    cudaFuncSetAttribute(gemm_proj_resid_t, cudaFuncAttributeMaxDynamicSharedMemorySize, PROJ_SMEM);
    cudaFuncSetAttribute(attn_spatial_mma, cudaFuncAttributeMaxDynamicSharedMemorySize, AT_SMEM);

    wconv4<<<8192, 256>>>(qkv_s_w, proj_s_w, qkv_t_w, proj_t_w);

    // spatial branch
    gn_norm_s<<<dim3(32,32), 256>>>(x, norm_s_w, norm_s_b);
    gemm_mma<<<dim3(12,144), 256, GEMM_SMEM>>>(gA, gW, qkv_s_b, gY, 1536);
    attn_spatial_mma<<<dim3(2,8,32), 288, AT_SMEM>>>(gY, gA);
    gemm_proj_resid<<<dim3(4,144), 256, PROJ_SMEM>>>(gA, gW + W_PS, proj_s_b, x, gX1);

    // temporal branch
    gn_norm_t<<<dim3(2,18,32), 256>>>(norm_t_w, norm_t_b);
    gemm_mma<<<dim3(12,144), 256, GEMM_SMEM>>>(gA, gW + W_QT, qkv_t_b, gY, 1536);
    attn_temporal<<<dim3(8,144), 256>>>(gY, rpk, rpv, gA);
    gemm_proj_resid_t<<<dim3(4,144), 256, PROJ_SMEM>>>(gA, gW + W_PT, proj_t_b, gX1, out);
}

// round 17
// speedup vs baseline: 1.0349x; 1.0349x over previous
#include <cuda_runtime.h>
#include <cuda_fp16.h>
#include <stdint.h>
#include <math.h>

#define TOK 18432
#define SCALE 0.35355339059327373f
#define W_PS  786432
#define W_QT  1048576
#define W_PT  1835008

static __device__ __half g_Y [TOK*1536];
static __device__ float g_x1[TOK*512];
static __device__ __half g_A[TOK*512];
static __device__ __half g_W[4096*512];

static __device__ __forceinline__ uint32_t s2u(const void* p) {
    uint32_t a;
    asm("{ .reg .u64 t; cvta.to.shared.u64 t, %1; cvt.u32.u64 %0, t; }" : "=r"(a) : "l"(p));
    return a;
}
static __device__ __forceinline__ void ldm4(uint32_t* r, uint32_t addr) {
    asm volatile("ldmatrix.sync.aligned.m8n8.x4.shared.b16 {%0,%1,%2,%3}, [%4];"
        : "=r"(r[0]), "=r"(r[1]), "=r"(r[2]), "=r"(r[3]) : "r"(addr));
}
static __device__ __forceinline__ void ldm4t(uint32_t* r, uint32_t addr) {
    asm volatile("ldmatrix.sync.aligned.m8n8.x4.trans.shared.b16 {%0,%1,%2,%3}, [%4];"
        : "=r"(r[0]), "=r"(r[1]), "=r"(r[2]), "=r"(r[3]) : "r"(addr));
}
static __device__ __forceinline__ void mma16816(float* d, const uint32_t* a, uint32_t b0, uint32_t b1) {
    asm volatile("mma.sync.aligned.m16n8k16.row.col.f32.f16.f16.f32 "
        "{%0,%1,%2,%3}, {%4,%5,%6,%7}, {%8,%9}, {%0,%1,%2,%3};"
        : "+f"(d[0]), "+f"(d[1]), "+f"(d[2]), "+f"(d[3])
        : "r"(a[0]), "r"(a[1]), "r"(a[2]), "r"(a[3]), "r"(b0), "r"(b1));
}
static __device__ __forceinline__ void cpasync16(uint32_t saddr, const void* g) {
    asm volatile("cp.async.cg.shared.global [%0], [%1], 16;" :: "r"(saddr), "l"(g));
}
static __device__ __forceinline__ uint32_t packh(float a, float b) {
    __half2 t = __floats2half2_rn(a, b);
    return *reinterpret_cast<uint32_t*>(&t);
}

// ---------------- fused spatial GN ----------------
__global__ __launch_bounds__(256) void gn_norm_s(const float* __restrict__ x,
        const float* __restrict__ gw, const float* __restrict__ gb) {
    __shared__ float buf[9216];
    __shared__ float rs[8], rss[8], red[2], sgw[16], sgb[16];
    int bt = blockIdx.x, g = blockIdx.y;
    int b = bt >> 4, t = bt & 15;
    const float* base = x + ((size_t)(b*512 + g*16))*9216 + (size_t)t*576;
    float s = 0.f, ss = 0.f;
    for (int e = threadIdx.x; e < 9216; e += 256) {
        int cc = e / 576, hw = e - cc*576;
        float v = base[(size_t)cc*9216 + hw];
        buf[e] = v;
        s += v; ss += v*v;
    }
    if (threadIdx.x < 16) {
        sgw[threadIdx.x] = gw[g*16 + threadIdx.x];
        sgb[threadIdx.x] = gb[g*16 + threadIdx.x];
    }
    #pragma unroll
    for (int o = 16; o; o >>= 1) {
        s  += __shfl_xor_sync(0xffffffffu, s,  o);
        ss += __shfl_xor_sync(0xffffffffu, ss, o);
    }
    int w = threadIdx.x >> 5;
    if ((threadIdx.x & 31) == 0) { rs[w] = s; rss[w] = ss; }
    __syncthreads();
    if (threadIdx.x == 0) {
        s = 0.f; ss = 0.f;
        #pragma unroll
        for (int i = 0; i < 8; i++) { s += rs[i]; ss += rss[i]; }
        float mean = s * (1.f/9216.f);
        float var  = ss * (1.f/9216.f) - mean*mean;
        red[0] = mean; red[1] = rsqrtf(var + 1e-5f);
    }
    __syncthreads();
    float mean = red[0], rstd = red[1];
    for (int hw = threadIdx.x; hw < 576; hw += 256) {
        __half tmp[16];
        #pragma unroll
        for (int cc = 0; cc < 16; cc++)
            tmp[cc] = __float2half_rn((buf[cc*576 + hw] - mean)*rstd*sgw[cc] + sgb[cc]);
        uint4* dst = (uint4*)(g_A + ((size_t)(bt*576 + hw))*512 + g*16);
        dst[0] = *(uint4*)&tmp[0];
        dst[1] = *(uint4*)&tmp[8];
    }
}

// ---------------- fused temporal GN ----------------
__global__ __launch_bounds__(256) void gn_norm_t(const float* __restrict__ gw,
                                                 const float* __restrict__ gb) {
    __shared__ float buf[16*16*33];
    __shared__ float part[8][32], partss[8][32], stat[2][32], sgw[16], sgb[16];
    int b = blockIdx.x, hw0 = blockIdx.y*32, g = blockIdx.z;
    int hwl = threadIdx.x & 31, slice = threadIdx.x >> 5;
    float s = 0.f, ss = 0.f;
    #pragma unroll
    for (int i = 0; i < 32; i++) {
        int p = slice*32 + i;
        int cc = p >> 4, t = p & 15;
        float v = g_x1[(((size_t)(b*512 + g*16 + cc))*16 + t)*576 + hw0 + hwl];
        buf[(cc*16 + t)*33 + hwl] = v;
        s += v; ss += v*v;
    }
    part[slice][hwl] = s;
    partss[slice][hwl] = ss;
    if (threadIdx.x >= 64 && threadIdx.x < 80) {
        sgw[threadIdx.x-64] = gw[g*16 + threadIdx.x-64];
        sgb[threadIdx.x-64] = gb[g*16 + threadIdx.x-64];
    }
    __syncthreads();
    if (threadIdx.x < 32) {
        float ts = 0.f, tss = 0.f;
        #pragma unroll
        for (int k = 0; k < 8; k++) { ts += part[k][threadIdx.x]; tss += partss[k][threadIdx.x]; }
        float mean = ts*(1.f/256.f);
        float var  = tss*(1.f/256.f) - mean*mean;
        stat[0][threadIdx.x] = mean;
        stat[1][threadIdx.x] = rsqrtf(var + 1e-5f);
    }
    __syncthreads();
    for (int pp = threadIdx.x; pp < 512; pp += 256) {
        int h2 = pp >> 4, t = pp & 15;
        float mean = stat[0][h2], rstd = stat[1][h2];
        __half tmp[16];
        #pragma unroll
        for (int cc = 0; cc < 16; cc++)
            tmp[cc] = __float2half_rn((buf[(cc*16 + t)*33 + h2] - mean)*rstd*sgw[cc] + sgb[cc]);
        uint4* dst = (uint4*)(g_A + ((size_t)((b*576 + hw0 + h2)*16 + t))*512 + g*16);
        dst[0] = *(uint4*)&tmp[0];
        dst[1] = *(uint4*)&tmp[8];
    }
}

// ---------------- weight convert ----------------
__global__ void wconv4(const float* __restrict__ wqs, const float* __restrict__ wps,
                       const float* __restrict__ wqt, const float* __restrict__ wpt) {
    int i = blockIdx.x*256 + threadIdx.x;
    float v;
    if (i < W_PS)       v = wqs[i];
    else if (i < W_QT)  v = wps[i - W_PS];
    else if (i < W_PT)  v = wqt[i - W_QT];
    else                v = wpt[i - W_PT];
    g_W[i] = __float2half_rn(v);
}

// ---------------- fp16 HMMA GEMM, cp.async 2-stage, fp16 output (qkv) ----------------
#define SPAD 72
#define GEMM_SMEM (2*36864)
#define PROJ_SMEM 73728
__global__ __launch_bounds__(256) void gemm_mma(
    const __half* __restrict__ A, const __half* __restrict__ B,
    const float* __restrict__ bias, __half* __restrict__ Y, int N) {
    extern __shared__ __half sm[];
    uint32_t smb = s2u(sm);
    int tid = threadIdx.x, wid = tid >> 5, lane = tid & 31;
    int wm = wid >> 2, wn = wid & 3;
    int m0 = blockIdx.y*128, n0 = blockIdx.x*128;
    const __half* pA = A + (size_t)m0*512;
    const __half* pB = B + (size_t)n0*512;

    float acc[4][4][4];
    #pragma unroll
    for (int i = 0; i < 4; i++)
        #pragma unroll
        for (int j = 0; j < 4; j++)
            #pragma unroll
            for (int k = 0; k < 4; k++) acc[i][j][k] = 0.f;

    int lrow = lane & 15, lcol = (lane >> 4) << 3;
    uint32_t aoff = (uint32_t)(( (wm*64 + lrow) * SPAD + lcol ) * 2);
    uint32_t boff = (uint32_t)(( (wn*32 + lrow) * SPAD + lcol ) * 2 + 18432);

    #pragma unroll
    for (int i = 0; i < 4; i++) {
        int idx = tid + i*256;
        int r = idx >> 3, c8 = (idx & 7) << 3;
        size_t go = (size_t)r*512 + c8;
        uint32_t so = smb + (uint32_t)((r*SPAD + c8)*2);
        cpasync16(so,         pA + go);
        cpasync16(so + 18432, pB + go);
    }
    asm volatile("cp.async.commit_group;" ::: "memory");

    for (int chunk = 0; chunk < 8; chunk++) {
        if (chunk < 7) {
            int koff = (chunk+1)*64;
            uint32_t stb = smb + ((chunk+1)&1)*36864;
            #pragma unroll
            for (int i = 0; i < 4; i++) {
                int idx = tid + i*256;
                int r = idx >> 3, c8 = (idx & 7) << 3;
                size_t go = (size_t)r*512 + koff + c8;
                uint32_t so = stb + (uint32_t)((r*SPAD + c8)*2);
                cpasync16(so,         pA + go);
                cpasync16(so + 18432, pB + go);
            }
            asm volatile("cp.async.commit_group;" ::: "memory");
            asm volatile("cp.async.wait_group 1;" ::: "memory");
        } else {
            asm volatile("cp.async.wait_group 0;" ::: "memory");
        }
        __syncthreads();
        uint32_t stb = smb + (chunk&1)*36864;
        uint32_t uA = stb + aoff, uB = stb + boff;
        #pragma unroll
        for (int k16 = 0; k16 < 4; k16++) {
            uint32_t kb = k16*32;
            uint32_t af[4][4], bf[2][4];
            #pragma unroll
            for (int mi = 0; mi < 4; mi++) ldm4(af[mi], uA + mi*16*SPAD*2 + kb);
            #pragma unroll
            for (int nj = 0; nj < 2; nj++) ldm4(bf[nj], uB + nj*16*SPAD*2 + kb);
            #pragma unroll
            for (int mi = 0; mi < 4; mi++)
                #pragma unroll
                for (int ni = 0; ni < 4; ni++) {
                    int nj = ni >> 1, hf = ni & 1;
                    mma16816(acc[mi][ni], af[mi], bf[nj][hf], bf[nj][hf+2]);
                }
        }
        __syncthreads();
    }
    int rbase = m0 + wm*64 + (lane >> 2);
    int cbase = n0 + wn*32 + (lane & 3)*2;
    #pragma unroll
    for (int mi = 0; mi < 4; mi++)
        #pragma unroll
        for (int ni = 0; ni < 4; ni++) {
            int col = cbase + ni*8;
            float2 bv = *(const float2*)(bias + col);
            int r0 = rbase + mi*16;
            *(uint32_t*)(Y + (size_t)r0*N + col)     = packh(acc[mi][ni][0] + bv.x, acc[mi][ni][1] + bv.y);
            *(uint32_t*)(Y + (size_t)(r0+8)*N + col) = packh(acc[mi][ni][2] + bv.x, acc[mi][ni][3] + bv.y);
        }
}

// ---- pipelined fp16 GEMM mainloop + fp32 ps staging (proj variants) ----
#define GEMM_BODY_P()                                                            \
    uint32_t smb = s2u(sm);                                                      \
    float acc[4][4][4];                                                          \
    _Pragma("unroll")                                                            \
    for (int i = 0; i < 4; i++)                                                  \
        _Pragma("unroll")                                                        \
        for (int j = 0; j < 4; j++)                                              \
            _Pragma("unroll")                                                    \
            for (int k = 0; k < 4; k++) acc[i][j][k] = 0.f;                      \
    int lrow = lane & 15, lcol = (lane >> 4) << 3;                               \
    uint32_t aoff = (uint32_t)(( (wm*64 + lrow) * SPAD + lcol ) * 2);            \
    uint32_t boff = (uint32_t)(( (wn*32 + lrow) * SPAD + lcol ) * 2 + 18432);    \
    _Pragma("unroll")                                                            \
    for (int i = 0; i < 4; i++) {                                                \
        int idx = tid + i*256;                                                   \
        int r = idx >> 3, c8 = (idx & 7) << 3;                                   \
        size_t go = (size_t)r*512 + c8;                                          \
        uint32_t so = smb + (uint32_t)((r*SPAD + c8)*2);                         \
        cpasync16(so,         pA + go);                                          \
        cpasync16(so + 18432, pB + go);                                          \
    }                                                                            \
    asm volatile("cp.async.commit_group;" ::: "memory");                         \
    for (int chunk = 0; chunk < 8; chunk++) {                                    \
        if (chunk < 7) {                                                         \
            int koff = (chunk+1)*64;                                             \
            uint32_t stb = smb + ((chunk+1)&1)*36864;                            \
            _Pragma("unroll")                                                    \
            for (int i = 0; i < 4; i++) {                                        \
                int idx = tid + i*256;                                           \
                int r = idx >> 3, c8 = (idx & 7) << 3;                           \
                size_t go = (size_t)r*512 + koff + c8;                           \
                uint32_t so = stb + (uint32_t)((r*SPAD + c8)*2);                 \
                cpasync16(so,         pA + go);                                  \
                cpasync16(so + 18432, pB + go);                                  \
            }                                                                    \
            asm volatile("cp.async.commit_group;" ::: "memory");                 \
            asm volatile("cp.async.wait_group 1;" ::: "memory");                 \
        } else {                                                                 \
            asm volatile("cp.async.wait_group 0;" ::: "memory");                 \
        }                                                                        \
        __syncthreads();                                                         \
        uint32_t stb = smb + (chunk&1)*36864;                                    \
        uint32_t uA = stb + aoff, uB = stb + boff;                               \
        _Pragma("unroll")                                                        \
        for (int k16 = 0; k16 < 4; k16++) {                                      \
            uint32_t kb = k16*32;                                                \
            uint32_t af[4][4], bf[2][4];                                         \
            _Pragma("unroll")                                                    \
            for (int mi = 0; mi < 4; mi++) ldm4(af[mi], uA + mi*16*SPAD*2 + kb); \
            _Pragma("unroll")                                                    \
            for (int nj = 0; nj < 2; nj++) ldm4(bf[nj], uB + nj*16*SPAD*2 + kb); \
            _Pragma("unroll")                                                    \
            for (int mi = 0; mi < 4; mi++)                                       \
                _Pragma("unroll")                                                \
                for (int ni = 0; ni < 4; ni++) {                                 \
                    int nj = ni >> 1, hf = ni & 1;                               \
                    mma16816(acc[mi][ni], af[mi], bf[nj][hf], bf[nj][hf+2]);     \
                }                                                                \
        }                                                                        \
        __syncthreads();                                                         \
    }                                                                            \
    float* ps = (float*)sm;                                                      \
    {                                                                            \
        int rb = wm*64 + (lane >> 2);                                            \
        int cb = wn*32 + (lane & 3)*2;                                           \
        _Pragma("unroll")                                                        \
        for (int mi = 0; mi < 4; mi++)                                           \
            _Pragma("unroll")                                                    \
            for (int ni = 0; ni < 4; ni++) {                                     \
                int c = cb + ni*8;                                               \
                float2 bv = *(const float2*)(bias + n0 + c);                     \
                int r0 = rb + mi*16;                                             \
                ps[c*132 + r0]         = acc[mi][ni][0] + bv.x;                  \
                ps[(c+1)*132 + r0]     = acc[mi][ni][1] + bv.y;                  \
                ps[c*132 + r0 + 8]     = acc[mi][ni][2] + bv.x;                  \
                ps[(c+1)*132 + r0 + 8] = acc[mi][ni][3] + bv.y;                  \
            }                                                                    \
    }                                                                            \
    __syncthreads();

// ---- proj_s GEMM + fused spatial residual: x1 = x + C^T ----
__global__ __launch_bounds__(256) void gemm_proj_resid(
    const __half* __restrict__ A, const __half* __restrict__ B,
    const float* __restrict__ bias, const float* __restrict__ x, float* __restrict__ x1) {
    extern __shared__ __half sm[];
    int tid = threadIdx.x, wid = tid >> 5, lane = tid & 31;
    int wm = wid >> 2, wn = wid & 3;
    int m0 = blockIdx.y*128, n0 = blockIdx.x*128;
    const __half* pA = A + (size_t)m0*512;
    const __half* pB = B + (size_t)n0*512;
    GEMM_BODY_P()
    {
        int w = tid >> 5;
        int r = (tid & 31)*4;
        int tk = m0 + r;
        int ns = tk / 576, hw = tk - ns*576;
        int b = ns >> 4, t = ns & 15;
        #pragma unroll
        for (int i = 0; i < 16; i++) {
            int c = w + i*8;
            float4 v = *(float4*)&ps[c*132 + r];
            size_t o = (((size_t)b*512 + n0 + c)*16 + t)*576 + hw;
            float4 xi = *(const float4*)(x + o);
            v.x += xi.x; v.y += xi.y; v.z += xi.z; v.w += xi.w;
            *(float4*)(x1 + o) = v;
        }
    }
}

// ---- proj_t GEMM + fused temporal residual: out = x1 + C^T ----
__global__ __launch_bounds__(256) void gemm_proj_resid_t(
    const __half* __restrict__ A, const __half* __restrict__ B,
    const float* __restrict__ bias, const float* __restrict__ xr, float* __restrict__ outp) {
    extern __shared__ __half sm[];
    int tid = threadIdx.x, wid = tid >> 5, lane = tid & 31;
    int wm = wid >> 2, wn = wid & 3;
    int m0 = blockIdx.y*128, n0 = blockIdx.x*128;
    const __half* pA = A + (size_t)m0*512;
    const __half* pB = B + (size_t)n0*512;
    GEMM_BODY_P()
    {
        int ns2 = m0 >> 4;
        int b = ns2 / 576, hw0 = ns2 - b*576;
        int t = tid & 15;
        #pragma unroll
        for (int it = 0; it < 8; it++) {
            int c = it*16 + (tid >> 4);
            float v[8];
            #pragma unroll
            for (int hwl = 0; hwl < 8; hwl++)
                v[hwl] = ps[c*132 + hwl*16 + t];
            size_t o = (((size_t)b*512 + n0 + c)*16 + t)*576 + hw0;
            float4 x0 = *(const float4*)(xr + o);
            float4 x1v = *(const float4*)(xr + o + 4);
            float4 o0 = { v[0]+x0.x, v[1]+x0.y, v[2]+x0.z, v[3]+x0.w };
            float4 o1 = { v[4]+x1v.x, v[5]+x1v.y, v[6]+x1v.z, v[7]+x1v.w };
            *(float4*)(outp + o)     = o0;
            *(float4*)(outp + o + 4) = o1;
        }
    }
}

// ---------------- spatial attention: 144-row Q-tile, double-buffered K/V chunks ----------------
// block = (q-tile, h, ns), 288 threads (9 warps x 16 q-rows)
#define AT_SMEM ((144*72 + 4*64*72)*2)
__global__ __launch_bounds__(288) void attn_spatial_mma(const __half* __restrict__ Y,
        __half* __restrict__ O) {
    extern __shared__ __half sb[];
    __half* Qs = sb;                        // 144*72 halfs
    uint32_t sKb = s2u(sb + 144*72);        // 2 K buffers of 64*72
    uint32_t sVb = s2u(sb + 144*72 + 2*64*72);
    int q0 = blockIdx.x*144, h = blockIdx.y, ns = blockIdx.z;
    int tid = threadIdx.x, wid = tid >> 5, lane = tid & 31;

    {   // load Q (288 threads, 144 rows), exact 0.125 scale
        int row = tid >> 1, dh = (tid & 1)*32;
        const __half* src = Y + ((size_t)(ns*576 + q0 + row))*1536 + h*64 + dh;
        __half2 sc = __float2half2_rn(0.125f);
        #pragma unroll
        for (int j = 0; j < 8; j++) {
            uint2 u = *(const uint2*)(src + j*4);
            __half2 a0 = __hmul2(*(__half2*)&u.x, sc);
            __half2 a1 = __hmul2(*(__half2*)&u.y, sc);
            uint2 o = { *(uint32_t*)&a0, *(uint32_t*)&a1 };
            *(uint2*)(Qs + row*72 + dh + j*4) = o;
        }
    }
    float oacc[8][4];
    float l[2] = {0.f, 0.f};
    #pragma unroll
    for (int t = 0; t < 8; t++)
        #pragma unroll
        for (int e = 0; e < 4; e++) oacc[t][e] = 0.f;

    int lrow = lane & 15, lcol = (lane >> 4) << 3;
    uint32_t uQ = s2u(Qs) + ((wid*16 + lrow)*72 + lcol)*2;
    uint32_t lmoff = (uint32_t)((lrow*72 + lcol)*2);
    // K/V chunk loader: threads 0..255, row = tid>>2, 16 halfs each
    int krow = tid >> 2, kseg = (tid & 3)*16;
    uint32_t stoff = (uint32_t)((krow*72 + kseg)*2);
    bool loader = tid < 256;

    if (loader) {
        const __half* ksrc = Y + ((size_t)(ns*576 + krow))*1536 + 512 + h*64 + kseg;
        cpasync16(sKb + stoff,      ksrc);
        cpasync16(sKb + stoff + 16, ksrc + 8);
        cpasync16(sVb + stoff,      ksrc + 512);
        cpasync16(sVb + stoff + 16, ksrc + 520);
    }
    asm volatile("cp.async.commit_group;" ::: "memory");

    for (int ch = 0; ch < 9; ch++) {
        asm volatile("cp.async.wait_group 0;" ::: "memory");
        __syncthreads();
        if (ch < 8 && loader) {
            uint32_t bo = ((ch+1)&1)*9216;
            const __half* ksrc = Y + ((size_t)(ns*576 + (ch+1)*64 + krow))*1536 + 512 + h*64 + kseg;
            cpasync16(sKb + bo + stoff,      ksrc);
            cpasync16(sKb + bo + stoff + 16, ksrc + 8);
            cpasync16(sVb + bo + stoff,      ksrc + 512);
            cpasync16(sVb + bo + stoff + 16, ksrc + 520);
        }
        if (ch < 8) asm volatile("cp.async.commit_group;" ::: "memory");
        uint32_t bo = (ch&1)*9216;
        uint32_t uK = sKb + bo + lmoff;
        uint32_t uV = sVb + bo + lmoff;
        float sacc[8][4];
        #pragma unroll
        for (int t = 0; t < 8; t++)
            #pragma unroll
            for (int e = 0; e < 4; e++) sacc[t][e] = 0.f;
        #pragma unroll
        for (int k16 = 0; k16 < 4; k16++) {
            uint32_t kb = k16*32;
            uint32_t a4[4];
            ldm4(a4, uQ + kb);
            #pragma unroll
            for (int g = 0; g < 4; g++) {
                uint32_t k4[4];
                ldm4(k4, uK + g*16*144 + kb);
                mma16816(sacc[2*g],   a4, k4[0], k4[2]);
                mma16816(sacc[2*g+1], a4, k4[1], k4[3]);
            }
        }
        uint32_t phx[8][2];
        #pragma unroll
        for (int hf = 0; hf < 2; hf++) {
            float rs = 0.f;
            #pragma unroll
            for (int t = 0; t < 8; t++) {
                float p0 = __expf(sacc[t][2*hf]);
                float p1 = __expf(sacc[t][2*hf+1]);
                rs += p0 + p1;
                phx[t][hf] = packh(p0, p1);
            }
            rs += __shfl_xor_sync(0xffffffffu, rs, 1);
            rs += __shfl_xor_sync(0xffffffffu, rs, 2);
            l[hf] += rs;
        }
        #pragma unroll
        for (int g = 0; g < 4; g++) {
            uint32_t pa[4] = {phx[2*g][0], phx[2*g][1], phx[2*g+1][0], phx[2*g+1][1]};
            #pragma unroll
            for (int dt = 0; dt < 4; dt++) {
                uint32_t v4[4];
                ldm4t(v4, uV + g*16*144 + dt*32);
                mma16816(oacc[2*dt],   pa, v4[0], v4[1]);
                mma16816(oacc[2*dt+1], pa, v4[2], v4[3]);
            }
        }
        __syncthreads();
    }
    float inv0 = 1.f / l[0], inv1 = 1.f / l[1];
    int r0 = q0 + wid*16 + (lane >> 2);
    int col0 = h*64 + (lane & 3)*2;
    #pragma unroll
    for (int t = 0; t < 8; t++) {
        int col = col0 + t*8;
        size_t offA = ((size_t)(ns*576 + r0))*512 + col;
        size_t offB = ((size_t)(ns*576 + r0 + 8))*512 + col;
        *(uint32_t*)(O + offA) = packh(oacc[t][0]*inv0, oacc[t][1]*inv0);
        *(uint32_t*)(O + offB) = packh(oacc[t][2]*inv1, oacc[t][3]*inv1);
    }
}

// ---------------- temporal attention (batched 8 samples per block) ----------------
#define TPS 8
__global__ __launch_bounds__(256) void attn_temporal(const __half* __restrict__ Y,
    const float* __restrict__ rpk, const float* __restrict__ rpv,
    __half* __restrict__ O) {
    __shared__ float qs[16][68], ks[16][68], vs[16][68];
    __shared__ float pk[33][68], pvt[33][68], wsm[16][20];
    int h = blockIdx.x, sg = blockIdx.y, tid = threadIdx.x;
    for (int i = tid; i < 33*64; i += 256) {
        pk [i>>6][i&63] = rpk[i];
        pvt[i>>6][i&63] = rpv[i];
    }
    for (int si = 0; si < TPS; si++) {
        int samp = sg*TPS + si;
        __syncthreads();
        {
            int t = tid >> 4, d0 = (tid & 15)*4;
            const __half* base = Y + ((size_t)(samp*16 + t))*1536 + h*64 + d0;
            #pragma unroll
            for (int part = 0; part < 3; part++) {
                uint2 u = *(const uint2*)(base + part*512);
                __half2 p0 = *(__half2*)&u.x, p1 = *(__half2*)&u.y;
                float* dst = (part == 0) ? &qs[t][d0] : (part == 1) ? &ks[t][d0] : &vs[t][d0];
                dst[0] = __half2float(p0.x); dst[1] = __half2float(p0.y);
                dst[2] = __half2float(p1.x); dst[3] = __half2float(p1.y);
            }
        }
        __syncthreads();
        {
            int t = tid >> 4, s = tid & 15;
            float wv = -1e30f;
            if (s <= t) {
                float a = 0.f, bb = 0.f;
                int ri = t - s + 16;
                for (int d = 0; d < 64; d++) {
                    a  += qs[t][d]*ks[s][d];
                    bb += qs[s][d]*pk[ri][d];
                }
                wv = 0.125f*a + SCALE*bb;
            }
            float mx = wv;
            #pragma unroll
            for (int o = 8; o; o >>= 1) mx = fmaxf(mx, __shfl_xor_sync(0xffffffffu, mx, o, 16));
            float e = (s <= t) ? __expf(wv - mx) : 0.f;
            float sum = e;
            #pragma unroll
            for (int o = 8; o; o >>= 1) sum += __shfl_xor_sync(0xffffffffu, sum, o, 16);
            wsm[t][s] = e / sum;
        }
        __syncthreads();
        {
            int t = tid >> 4, d0 = (tid & 15)*4;
            float o0 = 0.f, o1 = 0.f, o2 = 0.f, o3 = 0.f;
            #pragma unroll
            for (int s = 0; s < 16; s++) {
                float p = wsm[t][s];
                int ri = s - t + 16;
                o0 += p*(vs[s][d0+0] + pvt[ri][d0+0]);
                o1 += p*(vs[s][d0+1] + pvt[ri][d0+1]);
                o2 += p*(vs[s][d0+2] + pvt[ri][d0+2]);
                o3 += p*(vs[s][d0+3] + pvt[ri][d0+3]);
            }
            size_t off = ((size_t)(samp*16 + t))*512 + h*64 + d0;
            *(uint32_t*)(O + off)     = packh(o0, o1);
            *(uint32_t*)(O + off + 2) = packh(o2, o3);
        }
    }
}

extern "C" void kernel_launch(void* const* d_in, const int* in_sizes, int n_in,
                              void* d_out, int out_size) {
    const float* x        = (const float*)d_in[0];
    const float* norm_s_w = (const float*)d_in[1];
    const float* norm_s_b = (const float*)d_in[2];
    const float* qkv_s_w  = (const float*)d_in[3];
    const float* qkv_s_b  = (const float*)d_in[4];
    const float* proj_s_w = (const float*)d_in[5];
    const float* proj_s_b = (const float*)d_in[6];
    const float* norm_t_w = (const float*)d_in[7];
    const float* norm_t_b = (const float*)d_in[8];
    const float* qkv_t_w  = (const float*)d_in[9];
    const float* qkv_t_b  = (const float*)d_in[10];
    const float* proj_t_w = (const float*)d_in[11];
    const float* proj_t_b = (const float*)d_in[12];
    const float* rpk      = (const float*)d_in[13];
    const float* rpv      = (const float*)d_in[14];
    float* out = (float*)d_out;

    float *gX1;
    __half *gY, *gA, *gW;
    cudaGetSymbolAddress((void**)&gY,  g_Y);
    cudaGetSymbolAddress((void**)&gX1, g_x1);
    cudaGetSymbolAddress((void**)&gA,  g_A);
    cudaGetSymbolAddress((void**)&gW,  g_W);

    cudaFuncSetAttribute(gemm_mma, cudaFuncAttributeMaxDynamicSharedMemorySize, GEMM_SMEM);
    cudaFuncSetAttribute(gemm_proj_resid, cudaFuncAttributeMaxDynamicSharedMemorySize, PROJ_SMEM);
    cudaFuncSetAttribute(gemm_proj_resid_t, cudaFuncAttributeMaxDynamicSharedMemorySize, PROJ_SMEM);
    cudaFuncSetAttribute(attn_spatial_mma, cudaFuncAttributeMaxDynamicSharedMemorySize, AT_SMEM);

    wconv4<<<8192, 256>>>(qkv_s_w, proj_s_w, qkv_t_w, proj_t_w);

    // spatial branch
    gn_norm_s<<<dim3(32,32), 256>>>(x, norm_s_w, norm_s_b);
    gemm_mma<<<dim3(12,144), 256, GEMM_SMEM>>>(gA, gW, qkv_s_b, gY, 1536);
    attn_spatial_mma<<<dim3(4,8,32), 288, AT_SMEM>>>(gY, gA);
    gemm_proj_resid<<<dim3(4,144), 256, PROJ_SMEM>>>(gA, gW + W_PS, proj_s_b, x, gX1);

    // temporal branch
    gn_norm_t<<<dim3(2,18,32), 256>>>(norm_t_w, norm_t_b);
    gemm_mma<<<dim3(12,144), 256, GEMM_SMEM>>>(gA, gW + W_QT, qkv_t_b, gY, 1536);
    attn_temporal<<<dim3(8,144), 256>>>(gY, rpk, rpv, gA);
    gemm_proj_resid_t<<<dim3(4,144), 256, PROJ_SMEM>>>(gA, gW + W_PT, proj_t_b, gX1, out);
}